// round 3
// baseline (speedup 1.0000x reference)
#include <cuda_runtime.h>
#include <cstdint>

// ---------------------------------------------------------------------------
// TopK AutoEncoder: recon = (topk(A @ W_enc)) @ W_dec + b_pre
// Outputs (tuple order): recon [B,D], acts [B,H], z [B,H]
// B=4096, D=768, H=24576, k=32
// Strategy: exact-fp32 GEMM for acts; top-k selection made *true* via fp64
// refinement of a narrow boundary band (selection flips were the only error).
// ---------------------------------------------------------------------------

#define BM 128
#define BN 128
#define BK 16
#define TM 8
#define TN 8

// ---------------------- Kernel 1: encode GEMM (exact fp32) ------------------
__global__ void __launch_bounds__(256, 2)
encode_gemm_kernel(const float* __restrict__ A,
                   const float* __restrict__ W,
                   const float* __restrict__ bpre,
                   float* __restrict__ acts,
                   int Bsz, int D, int H)
{
    __shared__ float As[BK][BM + 4];
    __shared__ float Bs[BK][BN];

    const int tid = threadIdx.x;
    const int tx = tid & 15;
    const int ty = tid >> 4;
    const int m0 = blockIdx.y * BM;
    const int n0 = blockIdx.x * BN;

    float acc[TM][TN];
#pragma unroll
    for (int i = 0; i < TM; i++)
#pragma unroll
        for (int j = 0; j < TN; j++) acc[i][j] = 0.0f;

    for (int k0 = 0; k0 < D; k0 += BK) {
#pragma unroll
        for (int i = 0; i < 2; i++) {
            int idx = tid + i * 256;
            int row = idx >> 2;
            int kq  = (idx & 3) * 4;
            float4 av = *(const float4*)&A[(size_t)(m0 + row) * D + k0 + kq];
            float4 bv = *(const float4*)&bpre[k0 + kq];
            As[kq + 0][row] = av.x - bv.x;
            As[kq + 1][row] = av.y - bv.y;
            As[kq + 2][row] = av.z - bv.z;
            As[kq + 3][row] = av.w - bv.w;
        }
#pragma unroll
        for (int i = 0; i < 2; i++) {
            int idx = tid + i * 256;
            int kr  = idx >> 5;
            int nq  = (idx & 31) * 4;
            *(float4*)&Bs[kr][nq] = *(const float4*)&W[(size_t)(k0 + kr) * H + n0 + nq];
        }
        __syncthreads();

#pragma unroll
        for (int kk = 0; kk < BK; kk++) {
            float a[TM], b[TN];
            *(float4*)&a[0] = *(const float4*)&As[kk][ty * 4];
            *(float4*)&a[4] = *(const float4*)&As[kk][64 + ty * 4];
            *(float4*)&b[0] = *(const float4*)&Bs[kk][tx * 4];
            *(float4*)&b[4] = *(const float4*)&Bs[kk][64 + tx * 4];
#pragma unroll
            for (int i = 0; i < TM; i++)
#pragma unroll
                for (int j = 0; j < TN; j++)
                    acc[i][j] = fmaf(a[i], b[j], acc[i][j]);
        }
        __syncthreads();
    }

#pragma unroll
    for (int half = 0; half < 2; half++) {
#pragma unroll
        for (int i = 0; i < 4; i++) {
            int r = m0 + half * 64 + ty * 4 + i;
            float* p = &acts[(size_t)r * H + n0];
            int ai = half * 4 + i;
            *(float4*)&p[tx * 4]      = make_float4(acc[ai][0], acc[ai][1], acc[ai][2], acc[ai][3]);
            *(float4*)&p[64 + tx * 4] = make_float4(acc[ai][4], acc[ai][5], acc[ai][6], acc[ai][7]);
        }
    }
}

// ------------- Kernel 2: top-k (fp64-refined boundary) + z + decode ---------

__device__ __forceinline__ unsigned int f2key(float f) {
    unsigned int u = __float_as_uint(f);
    return (u & 0x80000000u) ? ~u : (u | 0x80000000u);
}
__device__ __forceinline__ float key2f(unsigned int u) {
    unsigned int b = (u & 0x80000000u) ? (u ^ 0x80000000u) : ~u;
    return __uint_as_float(b);
}

#define TOPK_THREADS 256
#define SEL_CAP 64
#define BAND_CAP 64
#define BAND_EPS 2e-3f

__global__ void __launch_bounds__(TOPK_THREADS)
topk_decode_kernel(const float* __restrict__ acts,
                   const float* __restrict__ A,
                   const float* __restrict__ Wenc,
                   const float* __restrict__ Wdec,
                   const float* __restrict__ bpre,
                   const int* __restrict__ kptr,
                   float* __restrict__ z,
                   float* __restrict__ recon,
                   int H, int D)
{
    extern __shared__ unsigned int su[];   // H keys
    __shared__ unsigned int hist[256];
    __shared__ unsigned int sh_prefix, sh_mask;
    __shared__ int sh_remaining;
    __shared__ int ncore, nband;
    __shared__ int   tki[SEL_CAP];
    __shared__ float tkv[SEL_CAP];
    __shared__ int    bidx[BAND_CAP];
    __shared__ float  bvalf[BAND_CAP];
    __shared__ double bvald[BAND_CAP];
    __shared__ unsigned char bsel[BAND_CAP];
    __shared__ int ntot;

    const int row = blockIdx.x;
    const int tid = threadIdx.x;
    const int lane = tid & 31;
    const int wid = tid >> 5;
    const int k = *kptr;
    const float* arow = acts + (size_t)row * H;

    for (int j = tid; j < H; j += TOPK_THREADS)
        su[j] = f2key(arow[j]);

    if (tid == 0) {
        sh_prefix = 0u; sh_mask = 0u; sh_remaining = k;
        ncore = 0; nband = 0; ntot = 0;
    }
    __syncthreads();

    // 4 MSD radix passes -> fp32 k-th largest key
#pragma unroll
    for (int shift = 24; shift >= 0; shift -= 8) {
        for (int i = tid; i < 256; i += TOPK_THREADS) hist[i] = 0u;
        __syncthreads();
        unsigned int pfx = sh_prefix, msk = sh_mask;
        for (int j = tid; j < H; j += TOPK_THREADS) {
            unsigned int u = su[j];
            if ((u & msk) == pfx)
                atomicAdd(&hist[(u >> shift) & 255u], 1u);
        }
        __syncthreads();
        if (tid == 0) {
            int rem = sh_remaining;
            for (int b = 255; b >= 0; b--) {
                int c = (int)hist[b];
                if (c >= rem) {
                    sh_prefix |= ((unsigned int)b) << shift;
                    sh_mask   |= 0xFFu << shift;
                    sh_remaining = rem;
                    break;
                }
                rem -= c;
            }
        }
        __syncthreads();
    }

    const float v_t = key2f(sh_prefix);

    // classify: core (surely top-k) / band (boundary, fp64-refine) / out
    for (int j = tid; j < H; j += TOPK_THREADS) {
        float f = key2f(su[j]);
        bool core = (f > v_t + BAND_EPS);
        bool band = (fabsf(f - v_t) <= BAND_EPS);
        z[(size_t)row * H + j] = core ? f : 0.0f;   // band fixed up below
        if (core) {
            int p = atomicAdd(&ncore, 1);
            if (p < SEL_CAP) { tki[p] = j; tkv[p] = f; }
        } else if (band) {
            int p = atomicAdd(&nband, 1);
            if (p < BAND_CAP) { bidx[p] = j; bvalf[p] = f; }
        }
    }
    __syncthreads();

    // fp64 re-evaluation of band members (one warp per member)
    const int nb = min(nband, BAND_CAP);
    for (int m = wid; m < nb; m += TOPK_THREADS / 32) {
        int j = bidx[m];
        double acc = 0.0;
        for (int d = lane; d < D; d += 32)
            acc += (double)(A[(size_t)row * D + d] - bpre[d]) *
                   (double)Wenc[(size_t)d * H + j];
#pragma unroll
        for (int o = 16; o > 0; o >>= 1)
            acc += __shfl_down_sync(0xFFFFFFFFu, acc, o);
        if (lane == 0) bvald[m] = acc;
    }
    __syncthreads();

    // thread 0: pick (k - ncore) band members by fp64 value desc, idx asc
    if (tid == 0) {
        int slots = k - min(ncore, SEL_CAP);
        if (slots < 0) slots = 0;
        if (slots > nb) slots = nb;
        for (int m = 0; m < nb; m++) bsel[m] = 0;
        int base = min(ncore, SEL_CAP);
        for (int s = 0; s < slots; s++) {
            int best = -1;
            for (int m = 0; m < nb; m++) {
                if (bsel[m]) continue;
                if (best < 0 ||
                    bvald[m] > bvald[best] ||
                    (bvald[m] == bvald[best] && bidx[m] < bidx[best]))
                    best = m;
            }
            bsel[best] = 1;
            if (base + s < SEL_CAP) { tki[base + s] = bidx[best]; tkv[base + s] = bvalf[best]; }
        }
        ntot = min(base + slots, SEL_CAP);
    }
    __syncthreads();

    // fix band z entries
    for (int m = tid; m < nb; m += TOPK_THREADS)
        z[(size_t)row * H + bidx[m]] = bsel[m] ? bvalf[m] : 0.0f;
    __syncthreads();

    // sparse decode: recon[row,d] = bpre[d] + sum_i tkv[i]*Wdec[tki[i], d]
    const int ns = ntot;
    for (int d = tid; d < D; d += TOPK_THREADS) {
        float acc = bpre[d];
        for (int i = 0; i < ns; i++)
            acc = fmaf(tkv[i], Wdec[(size_t)tki[i] * D + d], acc);
        recon[(size_t)row * D + d] = acc;
    }
}

// ---------------------------------------------------------------------------

extern "C" void kernel_launch(void* const* d_in, const int* in_sizes, int n_in,
                              void* d_out, int out_size)
{
    const float* A    = (const float*)d_in[0];
    const float* Wenc = (const float*)d_in[1];
    const float* Wdec = (const float*)d_in[2];
    const float* bpre = (const float*)d_in[3];
    const int*   kptr = (const int*)d_in[4];

    const int D = in_sizes[3];            // 768
    const int B = in_sizes[0] / D;        // 4096
    const int H = in_sizes[1] / D;        // 24576

    float* out   = (float*)d_out;
    float* recon = out;                                   // [B, D]
    float* acts  = out + (size_t)B * D;                   // [B, H]
    float* z     = out + (size_t)B * D + (size_t)B * H;   // [B, H]

    dim3 g1(H / BN, B / BM);
    encode_gemm_kernel<<<g1, 256>>>(A, Wenc, bpre, acts, B, D, H);

    size_t smem = (size_t)H * sizeof(unsigned int);
    static bool attr_set = false;
    if (!attr_set) {
        cudaFuncSetAttribute(topk_decode_kernel,
                             cudaFuncAttributeMaxDynamicSharedMemorySize,
                             (int)smem);
        attr_set = true;
    }
    topk_decode_kernel<<<B, TOPK_THREADS, smem>>>(acts, A, Wenc, Wdec, bpre,
                                                  kptr, z, recon, H, D);
}